// round 15
// baseline (speedup 1.0000x reference)
#include <cuda_runtime.h>
#include <cuda_fp16.h>
#include <cstdint>

#define EDIM   1024
#define BATCH  2
#define SEQ    2048
#define NHEADS 16
#define HDIM   64
#define WIN    128
#define MROWS  (BATCH*SEQ)

typedef __half hf;

// ---------------------------------------------------------------------------
// Persistent fp16 storage (allocation-free rule: __device__ globals)
// Split side (activations): hi+lo.  B side (weights, K, V): hi only.
// ---------------------------------------------------------------------------
__device__ hf g_qh[MROWS*EDIM], g_ql[MROWS*EDIM];
__device__ hf g_kh[MROWS*EDIM], g_kl[MROWS*EDIM];
__device__ hf g_vh[MROWS*EDIM], g_vl[MROWS*EDIM];
__device__ hf g_Wh[4][EDIM*EDIM];                    // Wq,Wk,Wv,Wo (hi only)
__device__ hf g_Qh[MROWS*EDIM], g_Ql[MROWS*EDIM];    // Q projected (split)
__device__ hf g_Kh[MROWS*EDIM];                      // K projected (hi only)
__device__ hf g_Vh[MROWS*EDIM];                      // V projected (hi only)
__device__ hf g_Ah[MROWS*EDIM], g_Al[MROWS*EDIM];    // attn out (split)

// ---------------------------------------------------------------------------
// Helpers
// ---------------------------------------------------------------------------
__device__ __forceinline__ uint32_t smem_u32(const void* p) {
    uint32_t a;
    asm("{ .reg .u64 t; cvta.to.shared.u64 t, %1; cvt.u32.u64 %0, t; }"
        : "=r"(a) : "l"(p));
    return a;
}
__device__ __forceinline__ void cpa16(uint32_t dst, const void* src) {
    asm volatile("cp.async.cg.shared.global [%0], [%1], 16;"
                 :: "r"(dst), "l"(src) : "memory");
}
#define CP_COMMIT() asm volatile("cp.async.commit_group;" ::: "memory")
#define CP_WAIT0()  asm volatile("cp.async.wait_group 0;" ::: "memory")
#define CP_WAIT1()  asm volatile("cp.async.wait_group 1;" ::: "memory")
#define CP_WAIT2()  asm volatile("cp.async.wait_group 2;" ::: "memory")

__device__ __forceinline__ void ldsm4(uint32_t* r, uint32_t addr) {
    asm volatile("ldmatrix.sync.aligned.m8n8.x4.shared.b16 {%0,%1,%2,%3}, [%4];"
                 : "=r"(r[0]), "=r"(r[1]), "=r"(r[2]), "=r"(r[3]) : "r"(addr));
}
__device__ __forceinline__ void ldsm4t(uint32_t* r, uint32_t addr) {
    asm volatile("ldmatrix.sync.aligned.m8n8.x4.trans.shared.b16 {%0,%1,%2,%3}, [%4];"
                 : "=r"(r[0]), "=r"(r[1]), "=r"(r[2]), "=r"(r[3]) : "r"(addr));
}
__device__ __forceinline__ void mma16816(float* c, const uint32_t* a,
                                         const uint32_t* b) {
    asm volatile(
        "mma.sync.aligned.m16n8k16.row.col.f32.f16.f16.f32 "
        "{%0,%1,%2,%3}, {%4,%5,%6,%7}, {%8,%9}, {%0,%1,%2,%3};"
        : "+f"(c[0]), "+f"(c[1]), "+f"(c[2]), "+f"(c[3])
        : "r"(a[0]), "r"(a[1]), "r"(a[2]), "r"(a[3]), "r"(b[0]), "r"(b[1]));
}

__device__ __forceinline__ void split4h(float4 v, uint2& hi, uint2& lo) {
    __half2 h0 = __floats2half2_rn(v.x, v.y);
    __half2 h1 = __floats2half2_rn(v.z, v.w);
    float2 f0 = __half22float2(h0);
    float2 f1 = __half22float2(h1);
    __half2 l0 = __floats2half2_rn(v.x - f0.x, v.y - f0.y);
    __half2 l1 = __floats2half2_rn(v.z - f1.x, v.w - f1.y);
    hi.x = *(uint32_t*)&h0; hi.y = *(uint32_t*)&h1;
    lo.x = *(uint32_t*)&l0; lo.y = *(uint32_t*)&l1;
}
__device__ __forceinline__ uint2 cvt4h(float4 v) {
    __half2 h0 = __floats2half2_rn(v.x, v.y);
    __half2 h1 = __floats2half2_rn(v.z, v.w);
    uint2 r; r.x = *(uint32_t*)&h0; r.y = *(uint32_t*)&h1;
    return r;
}

// ---------------------------------------------------------------------------
// Pre-split kernels
// ---------------------------------------------------------------------------
__global__ void __launch_bounds__(256)
split_qkv_kernel(const float* __restrict__ q, const float* __restrict__ k,
                 const float* __restrict__ v)
{
    const float* src; hf *h, *l;
    if (blockIdx.y == 0)      { src = q; h = g_qh; l = g_ql; }
    else if (blockIdx.y == 1) { src = k; h = g_kh; l = g_kl; }
    else                      { src = v; h = g_vh; l = g_vl; }
    int i = (blockIdx.x * 256 + threadIdx.x) * 4;
    float4 val = *(const float4*)(src + i);
    uint2 hi, lo;
    split4h(val, hi, lo);
    *(uint2*)(h + i) = hi;
    *(uint2*)(l + i) = lo;
}

__global__ void __launch_bounds__(256)
split_w_kernel(const float* __restrict__ Wq, const float* __restrict__ Wk,
               const float* __restrict__ Wv, const float* __restrict__ Wo)
{
    const float* src;
    if (blockIdx.y == 0)      src = Wq;
    else if (blockIdx.y == 1) src = Wk;
    else if (blockIdx.y == 2) src = Wv;
    else                      src = Wo;
    hf* h = g_Wh[blockIdx.y];
    int i = (blockIdx.x * 256 + threadIdx.x) * 4;
    float4 val = *(const float4*)(src + i);
    *(uint2*)(h + i) = cvt4h(val);
}

// ===========================================================================
// fp16 2-product cp.async pipelined GEMM (R7 structure):
//   C = A @ W^T + bias,  A split (Ah+Al), W hi only.
// CTA tile 128x128, BK=32, NSTAGE=3, 8 warps (4Mx2N), m16n8k16.
// OMODE: 0 = fp32 C, 1 = split fp16 Ch+Cl, 2 = fp16 Ch only.
// ===========================================================================
#define GBM 128
#define GBN 128
#define GBK 32
#define TILE_B 8192                  // 128 rows x 32 fp16 (64B rows)
#define STAGE_B (3*TILE_B)           // Ah, Al, Wh
#define NSTAGE 3
#define GEMM_SMEM_BYTES (NSTAGE*STAGE_B)   // 73728

__device__ __forceinline__ uint32_t swz(uint32_t row, uint32_t kbyte) {
    uint32_t chunk = ((kbyte >> 4) ^ ((row >> 1) & 3u)) & 3u;
    return row * 64u + chunk * 16u + (kbyte & 15u);
}

template<int OMODE>
__device__ __forceinline__ void gemm_async(const hf* __restrict__ Ah,
                                           const hf* __restrict__ Al,
                                           const hf* __restrict__ Wh,
                                           const float* __restrict__ bias,
                                           float* __restrict__ C,
                                           hf* __restrict__ Ch,
                                           hf* __restrict__ Cl)
{
    extern __shared__ char gsmem[];
    __shared__ float s_bias[GBN];

    const int tid  = threadIdx.x;
    const int lane = tid & 31;
    const int wid  = tid >> 5;
    const int wm   = wid >> 1;
    const int wn   = wid & 1;
    const uint32_t sbase = smem_u32(gsmem);

    const int row0 = blockIdx.y * GBM;
    const int col0 = blockIdx.x * GBN;

    if (tid < GBN) s_bias[tid] = bias[col0 + tid];

    const int lrow = tid >> 2;
    const int lkc  = tid & 3;
    const hf* pA0 = Ah + (size_t)(row0 + lrow) * EDIM + lkc * 8;
    const hf* pA1 = Al + (size_t)(row0 + lrow) * EDIM + lkc * 8;
    const hf* pW0 = Wh + (size_t)(col0 + lrow) * EDIM + lkc * 8;
    const uint32_t off0 = swz((uint32_t)lrow, (uint32_t)lkc * 16u);
    const uint32_t off1 = swz((uint32_t)(lrow + 64), (uint32_t)lkc * 16u);
    const size_t rstep = (size_t)64 * EDIM;

    float acc[2][8][4];
#pragma unroll
    for (int mt = 0; mt < 2; mt++)
#pragma unroll
        for (int nt = 0; nt < 8; nt++)
#pragma unroll
            for (int j = 0; j < 4; j++) acc[mt][nt][j] = 0.f;

    const uint32_t lrowm = (uint32_t)(lane & 15);
    const uint32_t lkb   = (uint32_t)(lane & 16);

    const int NCHUNK = EDIM / GBK;

#pragma unroll
    for (int s = 0; s < NSTAGE - 1; s++) {
        const uint32_t sb = sbase + (uint32_t)s * STAGE_B;
        const int k0 = s * GBK;
        cpa16(sb + 0*TILE_B + off0, pA0 + k0);
        cpa16(sb + 0*TILE_B + off1, pA0 + rstep + k0);
        cpa16(sb + 1*TILE_B + off0, pA1 + k0);
        cpa16(sb + 1*TILE_B + off1, pA1 + rstep + k0);
        cpa16(sb + 2*TILE_B + off0, pW0 + k0);
        cpa16(sb + 2*TILE_B + off1, pW0 + rstep + k0);
        CP_COMMIT();
    }

    int buf = 0, nbuf = NSTAGE - 1;
    for (int c = 0; c < NCHUNK; c++) {
        if (c < NCHUNK - 1) { CP_WAIT1(); } else { CP_WAIT0(); }
        __syncthreads();

        if (c + NSTAGE - 1 < NCHUNK) {
            const uint32_t sb = sbase + (uint32_t)nbuf * STAGE_B;
            const int k0 = (c + NSTAGE - 1) * GBK;
            cpa16(sb + 0*TILE_B + off0, pA0 + k0);
            cpa16(sb + 0*TILE_B + off1, pA0 + rstep + k0);
            cpa16(sb + 1*TILE_B + off0, pA1 + k0);
            cpa16(sb + 1*TILE_B + off1, pA1 + rstep + k0);
            cpa16(sb + 2*TILE_B + off0, pW0 + k0);
            cpa16(sb + 2*TILE_B + off1, pW0 + rstep + k0);
            CP_COMMIT();
        }
        if (++nbuf == NSTAGE) nbuf = 0;

        const uint32_t bb = sbase + (uint32_t)buf * STAGE_B;
        if (++buf == NSTAGE) buf = 0;

#pragma unroll
        for (int k16 = 0; k16 < 2; k16++) {
            const uint32_t kb = (uint32_t)k16 * 32u + lkb;
            uint32_t aH[2][4], aL[2][4], bH[8][2];
#pragma unroll
            for (int mt = 0; mt < 2; mt++) {
                uint32_t r = (uint32_t)(wm*32 + mt*16) + lrowm;
                ldsm4(aH[mt], bb + 0*TILE_B + swz(r, kb));
                ldsm4(aL[mt], bb + 1*TILE_B + swz(r, kb));
            }
#pragma unroll
            for (int g = 0; g < 4; g++) {
                uint32_t r = (uint32_t)(wn*64 + g*16) + lrowm;
                uint32_t t[4];
                ldsm4(t, bb + 2*TILE_B + swz(r, kb));
                bH[g*2][0]   = t[0]; bH[g*2][1]   = t[2];
                bH[g*2+1][0] = t[1]; bH[g*2+1][1] = t[3];
            }
#pragma unroll
            for (int mt = 0; mt < 2; mt++)
#pragma unroll
                for (int nt = 0; nt < 8; nt++)
                    mma16816(acc[mt][nt], aH[mt], bH[nt]);
#pragma unroll
            for (int mt = 0; mt < 2; mt++)
#pragma unroll
                for (int nt = 0; nt < 8; nt++)
                    mma16816(acc[mt][nt], aL[mt], bH[nt]);
        }
    }

    const int erow = lane >> 2;
    const int ecol = (lane & 3) * 2;
#pragma unroll
    for (int mt = 0; mt < 2; mt++) {
        const int rbase = row0 + wm*32 + mt*16 + erow;
#pragma unroll
        for (int nt = 0; nt < 8; nt++) {
            const int cb = wn*64 + nt*8 + ecol;
            const float b0 = s_bias[cb], b1 = s_bias[cb+1];
            float v00 = acc[mt][nt][0] + b0, v01 = acc[mt][nt][1] + b1;
            float v10 = acc[mt][nt][2] + b0, v11 = acc[mt][nt][3] + b1;
            if (OMODE == 0) {
                float2 o0 = {v00, v01}, o1 = {v10, v11};
                *(float2*)&C[(size_t)rbase * EDIM + col0 + cb]       = o0;
                *(float2*)&C[(size_t)(rbase + 8) * EDIM + col0 + cb] = o1;
            } else if (OMODE == 1) {
                __half2 hp = __floats2half2_rn(v00, v01);
                float2 ff = __half22float2(hp);
                __half2 lp = __floats2half2_rn(v00 - ff.x, v01 - ff.y);
                *(uint32_t*)&Ch[(size_t)rbase*EDIM + col0 + cb] = *(uint32_t*)&hp;
                *(uint32_t*)&Cl[(size_t)rbase*EDIM + col0 + cb] = *(uint32_t*)&lp;
                hp = __floats2half2_rn(v10, v11);
                ff = __half22float2(hp);
                lp = __floats2half2_rn(v10 - ff.x, v11 - ff.y);
                *(uint32_t*)&Ch[(size_t)(rbase+8)*EDIM + col0 + cb] = *(uint32_t*)&hp;
                *(uint32_t*)&Cl[(size_t)(rbase+8)*EDIM + col0 + cb] = *(uint32_t*)&lp;
            } else {
                __half2 hp = __floats2half2_rn(v00, v01);
                *(uint32_t*)&Ch[(size_t)rbase*EDIM + col0 + cb] = *(uint32_t*)&hp;
                hp = __floats2half2_rn(v10, v11);
                *(uint32_t*)&Ch[(size_t)(rbase+8)*EDIM + col0 + cb] = *(uint32_t*)&hp;
            }
        }
    }
}

__global__ void __launch_bounds__(256)
proj_qkv_kernel_b(const float* __restrict__ bq, const float* __restrict__ bk,
                  const float* __restrict__ bv)
{
    if (blockIdx.z == 0)
        gemm_async<1>(g_qh, g_ql, g_Wh[0], bq, nullptr, g_Qh, g_Ql);
    else if (blockIdx.z == 1)
        gemm_async<2>(g_kh, g_kl, g_Wh[1], bk, nullptr, g_Kh, nullptr);
    else
        gemm_async<2>(g_vh, g_vl, g_Wh[2], bv, nullptr, g_Vh, nullptr);
}

__global__ void __launch_bounds__(256)
out_proj_kernel(const float* __restrict__ bo, float* __restrict__ out)
{
    gemm_async<0>(g_Ah, g_Al, g_Wh[3], bo, out, nullptr, nullptr);
}

// ===========================================================================
// fp16 2-product sliding-window attention (R7 + band-gated softmax loops).
// ===========================================================================
#define ATT_T 16384
#define ATT_CHUNK_B (2*ATT_T)
#define ATT_SMEM_BYTES (2*ATT_T + 3*ATT_CHUNK_B)   // 131072

__device__ __forceinline__ uint32_t swzA(uint32_t row, uint32_t cb) {
    return row * 128u + ((((cb >> 4) ^ (row & 7u)) & 7u) << 4) + (cb & 15u);
}

__device__ __forceinline__ void stage_one(const hf* __restrict__ src,
                                          uint32_t u, int tid)
{
#pragma unroll
    for (int it = 0; it < 4; it++) {
        int idx = tid + it * 256;
        int row = idx >> 3;
        int ch  = idx & 7;
        uint32_t off = swzA((uint32_t)row, (uint32_t)ch * 16u);
        cpa16(u + off, src + (size_t)row * EDIM + ch * 8);
    }
}

__global__ void __launch_bounds__(256, 1)
attn_kernel()
{
    extern __shared__ char asmem[];
    const uint32_t uQh = smem_u32(asmem);
    const uint32_t uQl = uQh + ATT_T;

    const int tid  = threadIdx.x;
    const int lane = tid & 31;
    const int wid  = tid >> 5;
    const int qb   = blockIdx.x;
    const int h    = blockIdx.y;
    const int b    = blockIdx.z;
    const int q0   = qb * 128;
    const int qw   = wid * 16;

    const size_t hb = (size_t)b*SEQ*EDIM + (size_t)h*HDIM;

    const int nkb = SEQ / 128;
    const int kb0 = (qb > 0) ? qb - 1 : 0;
    const int kb1 = (qb < nkb - 1) ? qb + 1 : nkb - 1;
    const int nch = kb1 - kb0 + 1;

    stage_one(g_Qh + hb + (size_t)q0*EDIM, uQh, tid);
    stage_one(g_Ql + hb + (size_t)q0*EDIM, uQl, tid);
    {
        const int j0 = kb0 * 128;
        const uint32_t cs = uQh + 2*ATT_T;
        stage_one(g_Kh + hb + (size_t)j0*EDIM, cs, tid);
        stage_one(g_Vh + hb + (size_t)j0*EDIM, cs + ATT_T, tid);
    }
    CP_COMMIT();
    {
        const int j0 = (kb0 + 1) * 128;
        const uint32_t cs = uQh + 2*ATT_T + ATT_CHUNK_B;
        stage_one(g_Kh + hb + (size_t)j0*EDIM, cs, tid);
        stage_one(g_Vh + hb + (size_t)j0*EDIM, cs + ATT_T, tid);
    }
    CP_COMMIT();
    if (nch == 3) {
        const int j0 = (kb0 + 2) * 128;
        const uint32_t cs = uQh + 2*ATT_T + 2*ATT_CHUNK_B;
        stage_one(g_Kh + hb + (size_t)j0*EDIM, cs, tid);
        stage_one(g_Vh + hb + (size_t)j0*EDIM, cs + ATT_T, tid);
        CP_COMMIT();
    }

    const int r0g = q0 + qw + (lane >> 2);
    float m0 = -1e30f, m1 = -1e30f, l0 = 0.f, l1 = 0.f;
    float oacc[8][4];
#pragma unroll
    for (int nt = 0; nt < 8; nt++)
#pragma unroll
        for (int j = 0; j < 4; j++) oacc[nt][j] = 0.f;

    const uint32_t aRow = (uint32_t)(qw + (lane & 15));
    const uint32_t aKb  = (uint32_t)(lane & 16);
    const uint32_t bRowOff = (uint32_t)((lane & 7) + ((lane & 16) ? 8 : 0));
    const uint32_t bKb  = (uint32_t)((lane & 8) ? 16 : 0);
    const uint32_t vRowOff = (uint32_t)((lane & 7) + ((lane & 8) ? 8 : 0));
    const uint32_t vKb  = (uint32_t)((lane & 16) ? 16 : 0);

    for (int ci = 0; ci < nch; ci++) {
        const int kb = kb0 + ci;
        const int j0 = kb * 128;
        const int rel = (kb - qb) * 128;
        const uint32_t uKh = uQh + 2*ATT_T + (uint32_t)ci * ATT_CHUNK_B;
        const uint32_t uVh = uKh + ATT_T;

        const int rem = nch - 1 - ci;
        if (rem == 2)      { CP_WAIT2(); }
        else if (rem == 1) { CP_WAIT1(); }
        else               { CP_WAIT0(); }
        __syncthreads();

        int lo = qw - WIN - rel;          if (lo < 0) lo = 0;
        int hi = qw + 15 + WIN + 1 - rel; if (hi > 128) hi = 128;
        const int t16lo = lo >> 4;
        const int t16hi = (hi + 15) >> 4;

        float sacc[16][4];
#pragma unroll
        for (int nt = 0; nt < 16; nt++)
#pragma unroll
            for (int j = 0; j < 4; j++) sacc[nt][j] = 0.f;

#pragma unroll
        for (int k16 = 0; k16 < 4; k16++) {
            const uint32_t kcb = (uint32_t)k16 * 32u + aKb;
            uint32_t aH[4], aL[4];
            ldsm4(aH, uQh + swzA(aRow, kcb));
            ldsm4(aL, uQl + swzA(aRow, kcb));
            const uint32_t kcbB = (uint32_t)k16 * 32u + bKb;
#pragma unroll
            for (int g = 0; g < 8; g++) {
                if (g < t16lo || g >= t16hi) continue;
                const uint32_t rr = (uint32_t)(g * 16) + bRowOff;
                uint32_t tH[4];
                ldsm4(tH, uKh + swzA(rr, kcbB));
                uint32_t b0h[2] = {tH[0], tH[1]}, b1h[2] = {tH[2], tH[3]};
                mma16816(sacc[2*g],   aH, b0h);
                mma16816(sacc[2*g+1], aH, b1h);
                mma16816(sacc[2*g],   aL, b0h);
                mma16816(sacc[2*g+1], aL, b1h);
            }
        }

        // ---- scale + mask + online softmax (band-gated) ----
        const int cquad = (lane & 3) << 1;
        float mx0 = -1e30f, mx1 = -1e30f;
#pragma unroll
        for (int nt = 0; nt < 16; nt++) {
            if ((nt >> 1) < t16lo || (nt >> 1) >= t16hi) continue;
            const int gj = j0 + nt*8 + cquad;
            int d00 = r0g - gj;     d00 = d00 < 0 ? -d00 : d00;
            int d01 = r0g - gj - 1; d01 = d01 < 0 ? -d01 : d01;
            int d10 = r0g + 8 - gj;     d10 = d10 < 0 ? -d10 : d10;
            int d11 = r0g + 8 - gj - 1; d11 = d11 < 0 ? -d11 : d11;
            sacc[nt][0] = (d00 > WIN) ? -1e30f : sacc[nt][0] * 0.125f;
            sacc[nt][1] = (d01 > WIN) ? -1e30f : sacc[nt][1] * 0.125f;
            sacc[nt][2] = (d10 > WIN) ? -1e30f : sacc[nt][2] * 0.125f;
            sacc[nt][3] = (d11 > WIN) ? -1e30f : sacc[nt][3] * 0.125f;
            mx0 = fmaxf(mx0, fmaxf(sacc[nt][0], sacc[nt][1]));
            mx1 = fmaxf(mx1, fmaxf(sacc[nt][2], sacc[nt][3]));
        }
        mx0 = fmaxf(mx0, __shfl_xor_sync(0xffffffffu, mx0, 1));
        mx0 = fmaxf(mx0, __shfl_xor_sync(0xffffffffu, mx0, 2));
        mx1 = fmaxf(mx1, __shfl_xor_sync(0xffffffffu, mx1, 1));
        mx1 = fmaxf(mx1, __shfl_xor_sync(0xffffffffu, mx1, 2));

        const float mn0 = fmaxf(m0, mx0);
        const float mn1 = fmaxf(m1, mx1);
        const float cr0 = __expf(m0 - mn0);
        const float cr1 = __expf(m1 - mn1);
        float rs0 = 0.f, rs1 = 0.f;
#pragma unroll
        for (int nt = 0; nt < 16; nt++) {
            if ((nt >> 1) < t16lo || (nt >> 1) >= t16hi) continue;
            float p0 = __expf(sacc[nt][0] - mn0);
            float p1 = __expf(sacc[nt][1] - mn0);
            float p2 = __expf(sacc[nt][2] - mn1);
            float p3 = __expf(sacc[nt][3] - mn1);
            sacc[nt][0] = p0; sacc[nt][1] = p1;
            sacc[nt][2] = p2; sacc[nt][3] = p3;
            rs0 += p0 + p1; rs1 += p2 + p3;
        }
        rs0 += __shfl_xor_sync(0xffffffffu, rs0, 1);
        rs0 += __shfl_xor_sync(0xffffffffu, rs0, 2);
        rs1 += __shfl_xor_sync(0xffffffffu, rs1, 1);
        rs1 += __shfl_xor_sync(0xffffffffu, rs1, 2);
        l0 = l0 * cr0 + rs0;  m0 = mn0;
        l1 = l1 * cr1 + rs1;  m1 = mn1;
#pragma unroll
        for (int nt = 0; nt < 8; nt++) {
            oacc[nt][0] *= cr0; oacc[nt][1] *= cr0;
            oacc[nt][2] *= cr1; oacc[nt][3] *= cr1;
        }

#pragma unroll
        for (int kk = 0; kk < 8; kk++) {
            if (kk < t16lo || kk >= t16hi) continue;
            uint32_t ph[4], pl[4];
            {
                const float* p0 = sacc[2*kk];
                const float* p1 = sacc[2*kk + 1];
                __half2 hh; float2 ff;
                hh = __floats2half2_rn(p0[0], p0[1]); ph[0] = *(uint32_t*)&hh;
                ff = __half22float2(hh);
                float l0a = p0[0]-ff.x, l0b = p0[1]-ff.y;
                hh = __floats2half2_rn(p0[2], p0[3]); ph[1] = *(uint32_t*)&hh;
                ff = __half22float2(hh);
                float l1a = p0[2]-ff.x, l1b = p0[3]-ff.y;
                hh = __floats2half2_rn(p1[0], p1[1]); ph[2] = *(uint32_t*)&hh;
                ff = __half22float2(hh);
                float l2a = p1[0]-ff.x, l2b = p1[1]-ff.y;
                hh = __floats2half2_rn(p1[2], p1[3]); ph[3] = *(uint32_t*)&hh;
                ff = __half22float2(hh);
                float l3a = p1[2]-ff.x, l3b = p1[3]-ff.y;
                hh = __floats2half2_rn(l0a, l0b); pl[0] = *(uint32_t*)&hh;
                hh = __floats2half2_rn(l1a, l1b); pl[1] = *(uint32_t*)&hh;
                hh = __floats2half2_rn(l2a, l2b); pl[2] = *(uint32_t*)&hh;
                hh = __floats2half2_rn(l3a, l3b); pl[3] = *(uint32_t*)&hh;
            }
            const uint32_t vRow = (uint32_t)(kk * 16) + vRowOff;
#pragma unroll
            for (int g2 = 0; g2 < 4; g2++) {
                const uint32_t dcb = (uint32_t)g2 * 32u + vKb;
                uint32_t tH[4];
                ldsm4t(tH, uVh + swzA(vRow, dcb));
                uint32_t b0h[2] = {tH[0], tH[1]}, b1h[2] = {tH[2], tH[3]};
                mma16816(oacc[2*g2],   ph, b0h);
                mma16816(oacc[2*g2+1], ph, b1h);
                mma16816(oacc[2*g2],   pl, b0h);
                mma16816(oacc[2*g2+1], pl, b1h);
            }
        }
    }

    // ---- normalize + split-store ----
    const float inv0 = 1.0f / l0;
    const float inv1 = 1.0f / l1;
    const int dc = (lane & 3) << 1;
#pragma unroll
    for (int nt = 0; nt < 8; nt++) {
        const int dcol = nt*8 + dc;
        float v00 = oacc[nt][0]*inv0, v01 = oacc[nt][1]*inv0;
        float v10 = oacc[nt][2]*inv1, v11 = oacc[nt][3]*inv1;
        __half2 hp = __floats2half2_rn(v00, v01);
        float2 ff = __half22float2(hp);
        __half2 lp = __floats2half2_rn(v00 - ff.x, v01 - ff.y);
        *(uint32_t*)&g_Ah[hb + (size_t)r0g*EDIM + dcol] = *(uint32_t*)&hp;
        *(uint32_t*)&g_Al[hb + (size_t)r0g*EDIM + dcol] = *(uint32_t*)&lp;
        hp = __floats2half2_rn(v10, v11);
        ff = __half22float2(hp);
        lp = __floats2half2_rn(v10 - ff.x, v11 - ff.y);
        *(uint32_t*)&g_Ah[hb + (size_t)(r0g+8)*EDIM + dcol] = *(uint32_t*)&hp;
        *(uint32_t*)&g_Al[hb + (size_t)(r0g+8)*EDIM + dcol] = *(uint32_t*)&lp;
    }
}

// ---------------------------------------------------------------------------
extern "C" void kernel_launch(void* const* d_in, const int* in_sizes, int n_in,
                              void* d_out, int out_size)
{
    const float* q  = (const float*)d_in[0];
    const float* k  = (const float*)d_in[1];
    const float* v  = (const float*)d_in[2];
    const float* Wq = (const float*)d_in[3];
    const float* bq = (const float*)d_in[4];
    const float* Wk = (const float*)d_in[5];
    const float* bk = (const float*)d_in[6];
    const float* Wv = (const float*)d_in[7];
    const float* bv = (const float*)d_in[8];
    const float* Wo = (const float*)d_in[9];
    const float* bo = (const float*)d_in[10];
    float* out = (float*)d_out;

    cudaFuncSetAttribute(attn_kernel,
                         cudaFuncAttributeMaxDynamicSharedMemorySize,
                         ATT_SMEM_BYTES);
    cudaFuncSetAttribute(proj_qkv_kernel_b,
                         cudaFuncAttributeMaxDynamicSharedMemorySize,
                         GEMM_SMEM_BYTES);
    cudaFuncSetAttribute(out_proj_kernel,
                         cudaFuncAttributeMaxDynamicSharedMemorySize,
                         GEMM_SMEM_BYTES);

    split_qkv_kernel<<<dim3(MROWS*EDIM/1024, 3), 256>>>(q, k, v);
    split_w_kernel<<<dim3(EDIM*EDIM/1024, 4), 256>>>(Wq, Wk, Wv, Wo);

    dim3 gProj(EDIM/GBN, MROWS/GBM, 3);
    proj_qkv_kernel_b<<<gProj, 256, GEMM_SMEM_BYTES>>>(bq, bk, bv);

    dim3 gAttn(SEQ/128, NHEADS, BATCH);
    attn_kernel<<<gAttn, 256, ATT_SMEM_BYTES>>>();

    dim3 gOut(EDIM/GBN, MROWS/GBM, 1);
    out_proj_kernel<<<gOut, 256, GEMM_SMEM_BYTES>>>(bo, out);
}

// round 17
// speedup vs baseline: 1.2706x; 1.2706x over previous
#include <cuda_runtime.h>
#include <cuda_fp16.h>
#include <cstdint>

#define EDIM   1024
#define BATCH  2
#define SEQ    2048
#define NHEADS 16
#define HDIM   64
#define WIN    128
#define MROWS  (BATCH*SEQ)

typedef __half hf;

// ---------------------------------------------------------------------------
// Persistent fp16 storage (allocation-free rule: __device__ globals)
// q: hi+lo (2-product proj).  k,v: hi only (1-product proj).
// ---------------------------------------------------------------------------
__device__ hf g_qh[MROWS*EDIM], g_ql[MROWS*EDIM];
__device__ hf g_kh[MROWS*EDIM];
__device__ hf g_vh[MROWS*EDIM];
__device__ hf g_Wh[4][EDIM*EDIM];                    // Wq,Wk,Wv,Wo (hi only)
__device__ hf g_Qh[MROWS*EDIM], g_Ql[MROWS*EDIM];    // Q projected (split)
__device__ hf g_Kh[MROWS*EDIM];                      // K projected (hi only)
__device__ hf g_Vh[MROWS*EDIM];                      // V projected (hi only)
__device__ hf g_Ah[MROWS*EDIM], g_Al[MROWS*EDIM];    // attn out (split)

// ---------------------------------------------------------------------------
// Helpers
// ---------------------------------------------------------------------------
__device__ __forceinline__ uint32_t smem_u32(const void* p) {
    uint32_t a;
    asm("{ .reg .u64 t; cvta.to.shared.u64 t, %1; cvt.u32.u64 %0, t; }"
        : "=r"(a) : "l"(p));
    return a;
}
__device__ __forceinline__ void cpa16(uint32_t dst, const void* src) {
    asm volatile("cp.async.cg.shared.global [%0], [%1], 16;"
                 :: "r"(dst), "l"(src) : "memory");
}
#define CP_COMMIT() asm volatile("cp.async.commit_group;" ::: "memory")
#define CP_WAIT0()  asm volatile("cp.async.wait_group 0;" ::: "memory")
#define CP_WAIT1()  asm volatile("cp.async.wait_group 1;" ::: "memory")
#define CP_WAIT2()  asm volatile("cp.async.wait_group 2;" ::: "memory")

__device__ __forceinline__ void ldsm4(uint32_t* r, uint32_t addr) {
    asm volatile("ldmatrix.sync.aligned.m8n8.x4.shared.b16 {%0,%1,%2,%3}, [%4];"
                 : "=r"(r[0]), "=r"(r[1]), "=r"(r[2]), "=r"(r[3]) : "r"(addr));
}
__device__ __forceinline__ void ldsm4t(uint32_t* r, uint32_t addr) {
    asm volatile("ldmatrix.sync.aligned.m8n8.x4.trans.shared.b16 {%0,%1,%2,%3}, [%4];"
                 : "=r"(r[0]), "=r"(r[1]), "=r"(r[2]), "=r"(r[3]) : "r"(addr));
}
__device__ __forceinline__ void mma16816(float* c, const uint32_t* a,
                                         const uint32_t* b) {
    asm volatile(
        "mma.sync.aligned.m16n8k16.row.col.f32.f16.f16.f32 "
        "{%0,%1,%2,%3}, {%4,%5,%6,%7}, {%8,%9}, {%0,%1,%2,%3};"
        : "+f"(c[0]), "+f"(c[1]), "+f"(c[2]), "+f"(c[3])
        : "r"(a[0]), "r"(a[1]), "r"(a[2]), "r"(a[3]), "r"(b[0]), "r"(b[1]));
}

__device__ __forceinline__ void split4h(float4 v, uint2& hi, uint2& lo) {
    __half2 h0 = __floats2half2_rn(v.x, v.y);
    __half2 h1 = __floats2half2_rn(v.z, v.w);
    float2 f0 = __half22float2(h0);
    float2 f1 = __half22float2(h1);
    __half2 l0 = __floats2half2_rn(v.x - f0.x, v.y - f0.y);
    __half2 l1 = __floats2half2_rn(v.z - f1.x, v.w - f1.y);
    hi.x = *(uint32_t*)&h0; hi.y = *(uint32_t*)&h1;
    lo.x = *(uint32_t*)&l0; lo.y = *(uint32_t*)&l1;
}
__device__ __forceinline__ uint2 cvt4h(float4 v) {
    __half2 h0 = __floats2half2_rn(v.x, v.y);
    __half2 h1 = __floats2half2_rn(v.z, v.w);
    uint2 r; r.x = *(uint32_t*)&h0; r.y = *(uint32_t*)&h1;
    return r;
}

// ---------------------------------------------------------------------------
// Pre-split kernels.  q -> hi+lo;  k,v -> hi only.
// ---------------------------------------------------------------------------
__global__ void __launch_bounds__(256)
split_qkv_kernel(const float* __restrict__ q, const float* __restrict__ k,
                 const float* __restrict__ v)
{
    int i = (blockIdx.x * 256 + threadIdx.x) * 4;
    if (blockIdx.y == 0) {
        float4 val = *(const float4*)(q + i);
        uint2 hi, lo;
        split4h(val, hi, lo);
        *(uint2*)(g_qh + i) = hi;
        *(uint2*)(g_ql + i) = lo;
    } else if (blockIdx.y == 1) {
        *(uint2*)(g_kh + i) = cvt4h(*(const float4*)(k + i));
    } else {
        *(uint2*)(g_vh + i) = cvt4h(*(const float4*)(v + i));
    }
}

__global__ void __launch_bounds__(256)
split_w_kernel(const float* __restrict__ Wq, const float* __restrict__ Wk,
               const float* __restrict__ Wv, const float* __restrict__ Wo)
{
    const float* src;
    if (blockIdx.y == 0)      src = Wq;
    else if (blockIdx.y == 1) src = Wk;
    else if (blockIdx.y == 2) src = Wv;
    else                      src = Wo;
    hf* h = g_Wh[blockIdx.y];
    int i = (blockIdx.x * 256 + threadIdx.x) * 4;
    float4 val = *(const float4*)(src + i);
    *(uint2*)(h + i) = cvt4h(val);
}

// ===========================================================================
// fp16 cp.async pipelined GEMM (R7 structure), NPROD = 1 or 2 products:
//   C = A @ W^T + bias.  NPROD==2: A split Ah+Al.  NPROD==1: Ah only.
// CTA tile 128x128, BK=32, NSTAGE=3, 8 warps (4Mx2N), m16n8k16.
// OMODE: 0 = fp32 C, 1 = split fp16 Ch+Cl, 2 = fp16 Ch only.
// ===========================================================================
#define GBM 128
#define GBN 128
#define GBK 32
#define TILE_B 8192                  // 128 rows x 32 fp16 (64B rows)
#define STAGE_B (3*TILE_B)           // Ah, Al, Wh (Al slot unused if NPROD==1)
#define NSTAGE 3
#define GEMM_SMEM_BYTES (NSTAGE*STAGE_B)   // 73728

__device__ __forceinline__ uint32_t swz(uint32_t row, uint32_t kbyte) {
    uint32_t chunk = ((kbyte >> 4) ^ ((row >> 1) & 3u)) & 3u;
    return row * 64u + chunk * 16u + (kbyte & 15u);
}

template<int OMODE, int NPROD>
__device__ __forceinline__ void gemm_async(const hf* __restrict__ Ah,
                                           const hf* __restrict__ Al,
                                           const hf* __restrict__ Wh,
                                           const float* __restrict__ bias,
                                           float* __restrict__ C,
                                           hf* __restrict__ Ch,
                                           hf* __restrict__ Cl)
{
    extern __shared__ char gsmem[];
    __shared__ float s_bias[GBN];

    const int tid  = threadIdx.x;
    const int lane = tid & 31;
    const int wid  = tid >> 5;
    const int wm   = wid >> 1;
    const int wn   = wid & 1;
    const uint32_t sbase = smem_u32(gsmem);

    const int row0 = blockIdx.y * GBM;
    const int col0 = blockIdx.x * GBN;

    if (tid < GBN) s_bias[tid] = bias[col0 + tid];

    const int lrow = tid >> 2;
    const int lkc  = tid & 3;
    const hf* pA0 = Ah + (size_t)(row0 + lrow) * EDIM + lkc * 8;
    const hf* pA1 = (NPROD == 2) ? Al + (size_t)(row0 + lrow) * EDIM + lkc * 8
                                 : nullptr;
    const hf* pW0 = Wh + (size_t)(col0 + lrow) * EDIM + lkc * 8;
    const uint32_t off0 = swz((uint32_t)lrow, (uint32_t)lkc * 16u);
    const uint32_t off1 = swz((uint32_t)(lrow + 64), (uint32_t)lkc * 16u);
    const size_t rstep = (size_t)64 * EDIM;

    float acc[2][8][4];
#pragma unroll
    for (int mt = 0; mt < 2; mt++)
#pragma unroll
        for (int nt = 0; nt < 8; nt++)
#pragma unroll
            for (int j = 0; j < 4; j++) acc[mt][nt][j] = 0.f;

    const uint32_t lrowm = (uint32_t)(lane & 15);
    const uint32_t lkb   = (uint32_t)(lane & 16);

    const int NCHUNK = EDIM / GBK;

#pragma unroll
    for (int s = 0; s < NSTAGE - 1; s++) {
        const uint32_t sb = sbase + (uint32_t)s * STAGE_B;
        const int k0 = s * GBK;
        cpa16(sb + 0*TILE_B + off0, pA0 + k0);
        cpa16(sb + 0*TILE_B + off1, pA0 + rstep + k0);
        if (NPROD == 2) {
            cpa16(sb + 1*TILE_B + off0, pA1 + k0);
            cpa16(sb + 1*TILE_B + off1, pA1 + rstep + k0);
        }
        cpa16(sb + 2*TILE_B + off0, pW0 + k0);
        cpa16(sb + 2*TILE_B + off1, pW0 + rstep + k0);
        CP_COMMIT();
    }

    int buf = 0, nbuf = NSTAGE - 1;
    for (int c = 0; c < NCHUNK; c++) {
        if (c < NCHUNK - 1) { CP_WAIT1(); } else { CP_WAIT0(); }
        __syncthreads();

        if (c + NSTAGE - 1 < NCHUNK) {
            const uint32_t sb = sbase + (uint32_t)nbuf * STAGE_B;
            const int k0 = (c + NSTAGE - 1) * GBK;
            cpa16(sb + 0*TILE_B + off0, pA0 + k0);
            cpa16(sb + 0*TILE_B + off1, pA0 + rstep + k0);
            if (NPROD == 2) {
                cpa16(sb + 1*TILE_B + off0, pA1 + k0);
                cpa16(sb + 1*TILE_B + off1, pA1 + rstep + k0);
            }
            cpa16(sb + 2*TILE_B + off0, pW0 + k0);
            cpa16(sb + 2*TILE_B + off1, pW0 + rstep + k0);
            CP_COMMIT();
        }
        if (++nbuf == NSTAGE) nbuf = 0;

        const uint32_t bb = sbase + (uint32_t)buf * STAGE_B;
        if (++buf == NSTAGE) buf = 0;

#pragma unroll
        for (int k16 = 0; k16 < 2; k16++) {
            const uint32_t kb = (uint32_t)k16 * 32u + lkb;
            uint32_t aH[2][4], aL[2][4], bH[8][2];
#pragma unroll
            for (int mt = 0; mt < 2; mt++) {
                uint32_t r = (uint32_t)(wm*32 + mt*16) + lrowm;
                ldsm4(aH[mt], bb + 0*TILE_B + swz(r, kb));
                if (NPROD == 2)
                    ldsm4(aL[mt], bb + 1*TILE_B + swz(r, kb));
            }
#pragma unroll
            for (int g = 0; g < 4; g++) {
                uint32_t r = (uint32_t)(wn*64 + g*16) + lrowm;
                uint32_t t[4];
                ldsm4(t, bb + 2*TILE_B + swz(r, kb));
                bH[g*2][0]   = t[0]; bH[g*2][1]   = t[2];
                bH[g*2+1][0] = t[1]; bH[g*2+1][1] = t[3];
            }
#pragma unroll
            for (int mt = 0; mt < 2; mt++)
#pragma unroll
                for (int nt = 0; nt < 8; nt++)
                    mma16816(acc[mt][nt], aH[mt], bH[nt]);
            if (NPROD == 2) {
#pragma unroll
                for (int mt = 0; mt < 2; mt++)
#pragma unroll
                    for (int nt = 0; nt < 8; nt++)
                        mma16816(acc[mt][nt], aL[mt], bH[nt]);
            }
        }
    }

    const int erow = lane >> 2;
    const int ecol = (lane & 3) * 2;
#pragma unroll
    for (int mt = 0; mt < 2; mt++) {
        const int rbase = row0 + wm*32 + mt*16 + erow;
#pragma unroll
        for (int nt = 0; nt < 8; nt++) {
            const int cb = wn*64 + nt*8 + ecol;
            const float b0 = s_bias[cb], b1 = s_bias[cb+1];
            float v00 = acc[mt][nt][0] + b0, v01 = acc[mt][nt][1] + b1;
            float v10 = acc[mt][nt][2] + b0, v11 = acc[mt][nt][3] + b1;
            if (OMODE == 0) {
                float2 o0 = {v00, v01}, o1 = {v10, v11};
                *(float2*)&C[(size_t)rbase * EDIM + col0 + cb]       = o0;
                *(float2*)&C[(size_t)(rbase + 8) * EDIM + col0 + cb] = o1;
            } else if (OMODE == 1) {
                __half2 hp = __floats2half2_rn(v00, v01);
                float2 ff = __half22float2(hp);
                __half2 lp = __floats2half2_rn(v00 - ff.x, v01 - ff.y);
                *(uint32_t*)&Ch[(size_t)rbase*EDIM + col0 + cb] = *(uint32_t*)&hp;
                *(uint32_t*)&Cl[(size_t)rbase*EDIM + col0 + cb] = *(uint32_t*)&lp;
                hp = __floats2half2_rn(v10, v11);
                ff = __half22float2(hp);
                lp = __floats2half2_rn(v10 - ff.x, v11 - ff.y);
                *(uint32_t*)&Ch[(size_t)(rbase+8)*EDIM + col0 + cb] = *(uint32_t*)&hp;
                *(uint32_t*)&Cl[(size_t)(rbase+8)*EDIM + col0 + cb] = *(uint32_t*)&lp;
            } else {
                __half2 hp = __floats2half2_rn(v00, v01);
                *(uint32_t*)&Ch[(size_t)rbase*EDIM + col0 + cb] = *(uint32_t*)&hp;
                hp = __floats2half2_rn(v10, v11);
                *(uint32_t*)&Ch[(size_t)(rbase+8)*EDIM + col0 + cb] = *(uint32_t*)&hp;
            }
        }
    }
}

__global__ void __launch_bounds__(256)
proj_qkv_kernel_b(const float* __restrict__ bq, const float* __restrict__ bk,
                  const float* __restrict__ bv)
{
    if (blockIdx.z == 0)
        gemm_async<1, 2>(g_qh, g_ql, g_Wh[0], bq, nullptr, g_Qh, g_Ql);
    else if (blockIdx.z == 1)
        gemm_async<2, 1>(g_kh, nullptr, g_Wh[1], bk, nullptr, g_Kh, nullptr);
    else
        gemm_async<2, 1>(g_vh, nullptr, g_Wh[2], bv, nullptr, g_Vh, nullptr);
}

__global__ void __launch_bounds__(256)
out_proj_kernel(const float* __restrict__ bo, float* __restrict__ out)
{
    gemm_async<0, 2>(g_Ah, g_Al, g_Wh[3], bo, out, nullptr, nullptr);
}

// ===========================================================================
// fp16 2-product sliding-window attention (exact R7: ungated softmax).
// Q split hi/lo; K,V hi only. All chunks prefetched.
// ===========================================================================
#define ATT_T 16384
#define ATT_CHUNK_B (2*ATT_T)
#define ATT_SMEM_BYTES (2*ATT_T + 3*ATT_CHUNK_B)   // 131072

__device__ __forceinline__ uint32_t swzA(uint32_t row, uint32_t cb) {
    return row * 128u + ((((cb >> 4) ^ (row & 7u)) & 7u) << 4) + (cb & 15u);
}

__device__ __forceinline__ void stage_one(const hf* __restrict__ src,
                                          uint32_t u, int tid)
{
#pragma unroll
    for (int it = 0; it < 4; it++) {
        int idx = tid + it * 256;
        int row = idx >> 3;
        int ch  = idx & 7;
        uint32_t off = swzA((uint32_t)row, (uint32_t)ch * 16u);
        cpa16(u + off, src + (size_t)row * EDIM + ch * 8);
    }
}

__global__ void __launch_bounds__(256, 1)
attn_kernel()
{
    extern __shared__ char asmem[];
    const uint32_t uQh = smem_u32(asmem);
    const uint32_t uQl = uQh + ATT_T;

    const int tid  = threadIdx.x;
    const int lane = tid & 31;
    const int wid  = tid >> 5;
    const int qb   = blockIdx.x;
    const int h    = blockIdx.y;
    const int b    = blockIdx.z;
    const int q0   = qb * 128;
    const int qw   = wid * 16;

    const size_t hb = (size_t)b*SEQ*EDIM + (size_t)h*HDIM;

    const int nkb = SEQ / 128;
    const int kb0 = (qb > 0) ? qb - 1 : 0;
    const int kb1 = (qb < nkb - 1) ? qb + 1 : nkb - 1;
    const int nch = kb1 - kb0 + 1;

    stage_one(g_Qh + hb + (size_t)q0*EDIM, uQh, tid);
    stage_one(g_Ql + hb + (size_t)q0*EDIM, uQl, tid);
    {
        const int j0 = kb0 * 128;
        const uint32_t cs = uQh + 2*ATT_T;
        stage_one(g_Kh + hb + (size_t)j0*EDIM, cs, tid);
        stage_one(g_Vh + hb + (size_t)j0*EDIM, cs + ATT_T, tid);
    }
    CP_COMMIT();
    {
        const int j0 = (kb0 + 1) * 128;
        const uint32_t cs = uQh + 2*ATT_T + ATT_CHUNK_B;
        stage_one(g_Kh + hb + (size_t)j0*EDIM, cs, tid);
        stage_one(g_Vh + hb + (size_t)j0*EDIM, cs + ATT_T, tid);
    }
    CP_COMMIT();
    if (nch == 3) {
        const int j0 = (kb0 + 2) * 128;
        const uint32_t cs = uQh + 2*ATT_T + 2*ATT_CHUNK_B;
        stage_one(g_Kh + hb + (size_t)j0*EDIM, cs, tid);
        stage_one(g_Vh + hb + (size_t)j0*EDIM, cs + ATT_T, tid);
        CP_COMMIT();
    }

    const int r0g = q0 + qw + (lane >> 2);
    float m0 = -1e30f, m1 = -1e30f, l0 = 0.f, l1 = 0.f;
    float oacc[8][4];
#pragma unroll
    for (int nt = 0; nt < 8; nt++)
#pragma unroll
        for (int j = 0; j < 4; j++) oacc[nt][j] = 0.f;

    const uint32_t aRow = (uint32_t)(qw + (lane & 15));
    const uint32_t aKb  = (uint32_t)(lane & 16);
    const uint32_t bRowOff = (uint32_t)((lane & 7) + ((lane & 16) ? 8 : 0));
    const uint32_t bKb  = (uint32_t)((lane & 8) ? 16 : 0);
    const uint32_t vRowOff = (uint32_t)((lane & 7) + ((lane & 8) ? 8 : 0));
    const uint32_t vKb  = (uint32_t)((lane & 16) ? 16 : 0);

    for (int ci = 0; ci < nch; ci++) {
        const int kb = kb0 + ci;
        const int j0 = kb * 128;
        const int rel = (kb - qb) * 128;
        const uint32_t uKh = uQh + 2*ATT_T + (uint32_t)ci * ATT_CHUNK_B;
        const uint32_t uVh = uKh + ATT_T;

        const int rem = nch - 1 - ci;
        if (rem == 2)      { CP_WAIT2(); }
        else if (rem == 1) { CP_WAIT1(); }
        else               { CP_WAIT0(); }
        __syncthreads();

        int lo = qw - WIN - rel;          if (lo < 0) lo = 0;
        int hi = qw + 15 + WIN + 1 - rel; if (hi > 128) hi = 128;
        const int t16lo = lo >> 4;
        const int t16hi = (hi + 15) >> 4;

        float sacc[16][4];
#pragma unroll
        for (int nt = 0; nt < 16; nt++)
#pragma unroll
            for (int j = 0; j < 4; j++) sacc[nt][j] = 0.f;

#pragma unroll
        for (int k16 = 0; k16 < 4; k16++) {
            const uint32_t kcb = (uint32_t)k16 * 32u + aKb;
            uint32_t aH[4], aL[4];
            ldsm4(aH, uQh + swzA(aRow, kcb));
            ldsm4(aL, uQl + swzA(aRow, kcb));
            const uint32_t kcbB = (uint32_t)k16 * 32u + bKb;
#pragma unroll
            for (int g = 0; g < 8; g++) {
                if (g < t16lo || g >= t16hi) continue;
                const uint32_t rr = (uint32_t)(g * 16) + bRowOff;
                uint32_t tH[4];
                ldsm4(tH, uKh + swzA(rr, kcbB));
                uint32_t b0h[2] = {tH[0], tH[1]}, b1h[2] = {tH[2], tH[3]};
                mma16816(sacc[2*g],   aH, b0h);
                mma16816(sacc[2*g+1], aH, b1h);
                mma16816(sacc[2*g],   aL, b0h);
                mma16816(sacc[2*g+1], aL, b1h);
            }
        }

        // ---- scale + mask + online softmax (ungated, R7) ----
        const int cquad = (lane & 3) << 1;
        float mx0 = -1e30f, mx1 = -1e30f;
#pragma unroll
        for (int nt = 0; nt < 16; nt++) {
            const int gj = j0 + nt*8 + cquad;
            int d00 = r0g - gj;     d00 = d00 < 0 ? -d00 : d00;
            int d01 = r0g - gj - 1; d01 = d01 < 0 ? -d01 : d01;
            int d10 = r0g + 8 - gj;     d10 = d10 < 0 ? -d10 : d10;
            int d11 = r0g + 8 - gj - 1; d11 = d11 < 0 ? -d11 : d11;
            sacc[nt][0] = (d00 > WIN) ? -1e30f : sacc[nt][0] * 0.125f;
            sacc[nt][1] = (d01 > WIN) ? -1e30f : sacc[nt][1] * 0.125f;
            sacc[nt][2] = (d10 > WIN) ? -1e30f : sacc[nt][2] * 0.125f;
            sacc[nt][3] = (d11 > WIN) ? -1e30f : sacc[nt][3] * 0.125f;
            mx0 = fmaxf(mx0, fmaxf(sacc[nt][0], sacc[nt][1]));
            mx1 = fmaxf(mx1, fmaxf(sacc[nt][2], sacc[nt][3]));
        }
        mx0 = fmaxf(mx0, __shfl_xor_sync(0xffffffffu, mx0, 1));
        mx0 = fmaxf(mx0, __shfl_xor_sync(0xffffffffu, mx0, 2));
        mx1 = fmaxf(mx1, __shfl_xor_sync(0xffffffffu, mx1, 1));
        mx1 = fmaxf(mx1, __shfl_xor_sync(0xffffffffu, mx1, 2));

        const float mn0 = fmaxf(m0, mx0);
        const float mn1 = fmaxf(m1, mx1);
        const float cr0 = __expf(m0 - mn0);
        const float cr1 = __expf(m1 - mn1);
        float rs0 = 0.f, rs1 = 0.f;
#pragma unroll
        for (int nt = 0; nt < 16; nt++) {
            float p0 = __expf(sacc[nt][0] - mn0);
            float p1 = __expf(sacc[nt][1] - mn0);
            float p2 = __expf(sacc[nt][2] - mn1);
            float p3 = __expf(sacc[nt][3] - mn1);
            sacc[nt][0] = p0; sacc[nt][1] = p1;
            sacc[nt][2] = p2; sacc[nt][3] = p3;
            rs0 += p0 + p1; rs1 += p2 + p3;
        }
        rs0 += __shfl_xor_sync(0xffffffffu, rs0, 1);
        rs0 += __shfl_xor_sync(0xffffffffu, rs0, 2);
        rs1 += __shfl_xor_sync(0xffffffffu, rs1, 1);
        rs1 += __shfl_xor_sync(0xffffffffu, rs1, 2);
        l0 = l0 * cr0 + rs0;  m0 = mn0;
        l1 = l1 * cr1 + rs1;  m1 = mn1;
#pragma unroll
        for (int nt = 0; nt < 8; nt++) {
            oacc[nt][0] *= cr0; oacc[nt][1] *= cr0;
            oacc[nt][2] *= cr1; oacc[nt][3] *= cr1;
        }

#pragma unroll
        for (int kk = 0; kk < 8; kk++) {
            if (kk < t16lo || kk >= t16hi) continue;
            uint32_t ph[4], pl[4];
            {
                const float* p0 = sacc[2*kk];
                const float* p1 = sacc[2*kk + 1];
                __half2 hh; float2 ff;
                hh = __floats2half2_rn(p0[0], p0[1]); ph[0] = *(uint32_t*)&hh;
                ff = __half22float2(hh);
                float l0a = p0[0]-ff.x, l0b = p0[1]-ff.y;
                hh = __floats2half2_rn(p0[2], p0[3]); ph[1] = *(uint32_t*)&hh;
                ff = __half22float2(hh);
                float l1a = p0[2]-ff.x, l1b = p0[3]-ff.y;
                hh = __floats2half2_rn(p1[0], p1[1]); ph[2] = *(uint32_t*)&hh;
                ff = __half22float2(hh);
                float l2a = p1[0]-ff.x, l2b = p1[1]-ff.y;
                hh = __floats2half2_rn(p1[2], p1[3]); ph[3] = *(uint32_t*)&hh;
                ff = __half22float2(hh);
                float l3a = p1[2]-ff.x, l3b = p1[3]-ff.y;
                hh = __floats2half2_rn(l0a, l0b); pl[0] = *(uint32_t*)&hh;
                hh = __floats2half2_rn(l1a, l1b); pl[1] = *(uint32_t*)&hh;
                hh = __floats2half2_rn(l2a, l2b); pl[2] = *(uint32_t*)&hh;
                hh = __floats2half2_rn(l3a, l3b); pl[3] = *(uint32_t*)&hh;
            }
            const uint32_t vRow = (uint32_t)(kk * 16) + vRowOff;
#pragma unroll
            for (int g2 = 0; g2 < 4; g2++) {
                const uint32_t dcb = (uint32_t)g2 * 32u + vKb;
                uint32_t tH[4];
                ldsm4t(tH, uVh + swzA(vRow, dcb));
                uint32_t b0h[2] = {tH[0], tH[1]}, b1h[2] = {tH[2], tH[3]};
                mma16816(oacc[2*g2],   ph, b0h);
                mma16816(oacc[2*g2+1], ph, b1h);
                mma16816(oacc[2*g2],   pl, b0h);
                mma16816(oacc[2*g2+1], pl, b1h);
            }
        }
    }

    // ---- normalize + split-store ----
    const float inv0 = 1.0f / l0;
    const float inv1 = 1.0f / l1;
    const int dc = (lane & 3) << 1;
#pragma unroll
    for (int nt = 0; nt < 8; nt++) {
        const int dcol = nt*8 + dc;
        float v00 = oacc[nt][0]*inv0, v01 = oacc[nt][1]*inv0;
        float v10 = oacc[nt][2]*inv1, v11 = oacc[nt][3]*inv1;
        __half2 hp = __floats2half2_rn(v00, v01);
        float2 ff = __half22float2(hp);
        __half2 lp = __floats2half2_rn(v00 - ff.x, v01 - ff.y);
        *(uint32_t*)&g_Ah[hb + (size_t)r0g*EDIM + dcol] = *(uint32_t*)&hp;
        *(uint32_t*)&g_Al[hb + (size_t)r0g*EDIM + dcol] = *(uint32_t*)&lp;
        hp = __floats2half2_rn(v10, v11);
        ff = __half22float2(hp);
        lp = __floats2half2_rn(v10 - ff.x, v11 - ff.y);
        *(uint32_t*)&g_Ah[hb + (size_t)(r0g+8)*EDIM + dcol] = *(uint32_t*)&hp;
        *(uint32_t*)&g_Al[hb + (size_t)(r0g+8)*EDIM + dcol] = *(uint32_t*)&lp;
    }
}

// ---------------------------------------------------------------------------
extern "C" void kernel_launch(void* const* d_in, const int* in_sizes, int n_in,
                              void* d_out, int out_size)
{
    const float* q  = (const float*)d_in[0];
    const float* k  = (const float*)d_in[1];
    const float* v  = (const float*)d_in[2];
    const float* Wq = (const float*)d_in[3];
    const float* bq = (const float*)d_in[4];
    const float* Wk = (const float*)d_in[5];
    const float* bk = (const float*)d_in[6];
    const float* Wv = (const float*)d_in[7];
    const float* bv = (const float*)d_in[8];
    const float* Wo = (const float*)d_in[9];
    const float* bo = (const float*)d_in[10];
    float* out = (float*)d_out;

    cudaFuncSetAttribute(attn_kernel,
                         cudaFuncAttributeMaxDynamicSharedMemorySize,
                         ATT_SMEM_BYTES);
    cudaFuncSetAttribute(proj_qkv_kernel_b,
                         cudaFuncAttributeMaxDynamicSharedMemorySize,
                         GEMM_SMEM_BYTES);
    cudaFuncSetAttribute(out_proj_kernel,
                         cudaFuncAttributeMaxDynamicSharedMemorySize,
                         GEMM_SMEM_BYTES);

    split_qkv_kernel<<<dim3(MROWS*EDIM/1024, 3), 256>>>(q, k, v);
    split_w_kernel<<<dim3(EDIM*EDIM/1024, 4), 256>>>(Wq, Wk, Wv, Wo);

    dim3 gProj(EDIM/GBN, MROWS/GBM, 3);
    proj_qkv_kernel_b<<<gProj, 256, GEMM_SMEM_BYTES>>>(bq, bk, bv);

    dim3 gAttn(SEQ/128, NHEADS, BATCH);
    attn_kernel<<<gAttn, 256, ATT_SMEM_BYTES>>>();

    dim3 gOut(EDIM/GBN, MROWS/GBM, 1);
    out_proj_kernel<<<gOut, 256, GEMM_SMEM_BYTES>>>(bo, out);
}